// round 10
// baseline (speedup 1.0000x reference)
#include <cuda_runtime.h>
#include <cuda_bf16.h>
#include <math.h>

#define HID   1024
#define NB    256
#define L_SEQ 512
#define NH    (NB * HID)
#define NBLK  128
#define NTHR  256
#define NFRAG (512 * 64 * 32)

// packed B fragments: [0]=Whh0 hi [1]=Whh0 lo [2]=Wih1 hi [3]=Wih1 lo [4]=Whh1 hi [5]=Whh1 lo
__device__ uint2         g_Wp[6][NFRAG];
// h buffers: h0 even->[0,1] odd->[2,3]; h1 even->[4,5] odd->[6,7]  (hi,lo)
__device__ __nv_bfloat16 g_h[8][NH];
__device__ float         g_c0[NH], g_c1[NH];
__device__ unsigned      g_count = 0, g_gen = 0;

__device__ __forceinline__ float sigm(float x){ return __fdividef(1.f, 1.f + __expf(-x)); }
__device__ __forceinline__ float ftanh(float x){ float e=__expf(2.f*x); return 1.f-__fdividef(2.f,e+1.f); }
__device__ __forceinline__ int colmap(int p){ int s=p>>6, nl=p&63; return (nl&3)*HID + (s<<4) + (nl>>2); }
__device__ __forceinline__ unsigned pkbf(__nv_bfloat16 a,__nv_bfloat16 b){
    __nv_bfloat162 t; t.x=a; t.y=b; return *reinterpret_cast<unsigned*>(&t); }

__device__ __forceinline__ void grid_sync(){
    __syncthreads();
    if (threadIdx.x==0){
        __threadfence();
        unsigned g=*(volatile unsigned*)&g_gen;
        if (atomicAdd(&g_count,1u)==NBLK-1){ g_count=0; __threadfence(); atomicAdd(&g_gen,1u); }
        else while (*(volatile unsigned*)&g_gen==g){ __nanosleep(32); }
        __threadfence();
    }
    __syncthreads();
}

#define MMA(d,a,b0v,b1v) asm volatile( \
  "mma.sync.aligned.m16n8k16.row.col.f32.bf16.bf16.f32 {%0,%1,%2,%3},{%4,%5,%6,%7},{%8,%9},{%0,%1,%2,%3};" \
  : "+f"(d[0]),"+f"(d[1]),"+f"(d[2]),"+f"(d[3]) \
  : "r"(a[0]),"r"(a[1]),"r"(a[2]),"r"(a[3]),"r"(b0v),"r"(b1v))
#define LDSM4(r,addr) asm volatile( \
  "ldmatrix.sync.aligned.m8n8.x4.shared.b16 {%0,%1,%2,%3},[%4];" \
  : "=r"(r[0]),"=r"(r[1]),"=r"(r[2]),"=r"(r[3]) : "r"(addr))

#define ABUFB 10240u   // bytes per A buffer (128*40*2)
#define ABUFE 5120     // bf16 elements per A buffer

// GEMM-accumulate over K=1024.  Double-buffered smem A (register prefetch via
// __ldcg), register double-buffered B fragments, ONE __syncthreads per chunk.
// Hazard argument: store(i)->buf[i&1] is safe because every reader of that
// buffer (compute of chunk i-2) finished before sync(i-1), which precedes
// store(i) in every thread's program order.
__device__ __forceinline__ void gemm_pipe(
    const __nv_bfloat16* __restrict__ gh, const __nv_bfloat16* __restrict__ gl,
    const uint2* __restrict__ Bhi, const uint2* __restrict__ Blo,
    int jn0, int lane,
    __nv_bfloat16* pH, __nv_bfloat16* pL,   // this thread's smem store slot (buffer 0)
    unsigned aH, unsigned aL,               // ldmatrix base addr (buffer 0)
    float (&acc)[4][2][4])
{
    uint4 ph0=__ldcg((const uint4*)gh),     ph1=__ldcg((const uint4*)(gh+8));
    uint4 pl0=__ldcg((const uint4*)gl),     pl1=__ldcg((const uint4*)(gl+8));
    uint2 bhc[2][2], blc[2][2];
    #pragma unroll
    for (int h=0;h<2;++h)
        #pragma unroll
        for (int nt=0;nt<2;++nt){
            int idx=((jn0+nt)*64 + h)*32 + lane;
            bhc[h][nt]=Bhi[idx]; blc[h][nt]=Blo[idx];
        }

    #pragma unroll 1
    for (int i=0;i<32;++i){
        __nv_bfloat16* dH = pH + (i&1)*ABUFE;
        __nv_bfloat16* dL = pL + (i&1)*ABUFE;
        *(uint4*)dH = ph0; *(uint4*)(dH+8) = ph1;
        *(uint4*)dL = pl0; *(uint4*)(dL+8) = pl1;
        __syncthreads();                       // publishes chunk i

        uint2 bhn[2][2], bln[2][2];
        if (i<31){
            const __nv_bfloat16* gh2=gh+(i+1)*32;
            const __nv_bfloat16* gl2=gl+(i+1)*32;
            ph0=__ldcg((const uint4*)gh2); ph1=__ldcg((const uint4*)(gh2+8));
            pl0=__ldcg((const uint4*)gl2); pl1=__ldcg((const uint4*)(gl2+8));
            #pragma unroll
            for (int h=0;h<2;++h)
                #pragma unroll
                for (int nt=0;nt<2;++nt){
                    int idx=((jn0+nt)*64 + 2*(i+1)+h)*32 + lane;
                    bhn[h][nt]=Bhi[idx]; bln[h][nt]=Blo[idx];
                }
        }
        unsigned cb=(unsigned)(i&1)*ABUFB;
        #pragma unroll
        for (int h=0;h<2;++h){
            unsigned ah[4][4], al[4][4];
            #pragma unroll
            for (int mt=0;mt<4;++mt){
                LDSM4(ah[mt], aH+cb+mt*1280u+h*32u);
                LDSM4(al[mt], aL+cb+mt*1280u+h*32u);
            }
            #pragma unroll
            for (int mt=0;mt<4;++mt)
                #pragma unroll
                for (int nt=0;nt<2;++nt){
                    MMA(acc[mt][nt], ah[mt], bhc[h][nt].x, bhc[h][nt].y);
                    MMA(acc[mt][nt], ah[mt], blc[h][nt].x, blc[h][nt].y);
                    MMA(acc[mt][nt], al[mt], bhc[h][nt].x, bhc[h][nt].y);
                }
        }
        if (i<31){
            #pragma unroll
            for (int h=0;h<2;++h)
                #pragma unroll
                for (int nt=0;nt<2;++nt){ bhc[h][nt]=bhn[h][nt]; blc[h][nt]=bln[h][nt]; }
        }
    }
}

__global__ void __launch_bounds__(NTHR,1) lstm_tc3(
    const float* __restrict__ seq,
    const float* __restrict__ Wih0, const float* __restrict__ Whh0,
    const float* __restrict__ bih0, const float* __restrict__ bhh0,
    const float* __restrict__ Wih1, const float* __restrict__ Whh1,
    const float* __restrict__ bih1, const float* __restrict__ bhh1,
    const float* __restrict__ linW, const float* __restrict__ linb,
    float* __restrict__ out)
{
    __shared__ __nv_bfloat16 AsH[2][128][40], AsL[2][128][40];
    __shared__ float Xs[128][6], W6s[64][6];
    __shared__ __align__(16) float biasS0[64], biasS1[64];
    __shared__ float red[8];

    const int tid=threadIdx.x, bid=blockIdx.x, lane=tid&31, w=tid>>5;
    const int s=bid>>1, mb=(bid&1)*128;
    const int wm=(w&1)*64, wn=(w>>1)*16;
    const int jn0=s*8+(wn>>3);
    const int gq=lane>>2, iq=lane&3, odd=iq&1;

    // ---- pack weights (once) ----
    {
        const float* Wsrc[3]={Whh0,Wih1,Whh1};
        for (int f=bid*8+w; f<3*32768; f+=NBLK*8){
            int mat=f>>15, rem=f&32767, jn=rem>>6, kt=rem&63;
            int j=colmap(jn*8+(lane>>2));
            int k0=(kt<<4)+(lane&3)*2;
            const float* W=Wsrc[mat]+j*HID+k0;
            float2 w0=*(const float2*)W, w8=*(const float2*)(W+8);
            __nv_bfloat16 h0=__float2bfloat16(w0.x), h1=__float2bfloat16(w0.y);
            __nv_bfloat16 h2=__float2bfloat16(w8.x), h3=__float2bfloat16(w8.y);
            __nv_bfloat16 l0=__float2bfloat16(w0.x-__bfloat162float(h0));
            __nv_bfloat16 l1=__float2bfloat16(w0.y-__bfloat162float(h1));
            __nv_bfloat16 l2=__float2bfloat16(w8.x-__bfloat162float(h2));
            __nv_bfloat16 l3=__float2bfloat16(w8.y-__bfloat162float(h3));
            int idx=(jn*64+kt)*32+lane;
            g_Wp[mat*2  ][idx]=make_uint2(pkbf(h0,h1),pkbf(h2,h3));
            g_Wp[mat*2+1][idx]=make_uint2(pkbf(l0,l1),pkbf(l2,l3));
        }
    }
    // ---- zero h0[-1] (bufs 2,3), h1[-1] (bufs 6,7), cell states ----
    {
        int base=bid*(NH/NBLK); __nv_bfloat16 z=__float2bfloat16(0.f);
        for (int i=tid;i<NH/NBLK;i+=NTHR){
            g_h[2][base+i]=z; g_h[3][base+i]=z; g_h[6][base+i]=z; g_h[7][base+i]=z;
            g_c0[base+i]=0.f; g_c1[base+i]=0.f;
        }
    }
    if (tid<64){
        int j=colmap(s*64+tid);
        biasS0[tid]=bih0[j]+bhh0[j]; biasS1[tid]=bih1[j]+bhh1[j];
    }
    for (int i=tid;i<64*6;i+=NTHR){ int c=i/6,k=i-c*6; W6s[c][k]=Wih0[colmap(s*64+c)*6+k]; }
    grid_sync();

    // per-lane addresses
    const int srow=tid>>1, scol=(tid&1)*16;
    const int Aoff=srow*HID+scol;
    __nv_bfloat16* pH=&AsH[0][srow][scol];
    __nv_bfloat16* pL=&AsL[0][srow][scol];
    const int j8=lane>>3, r8=lane&7;
    const int alr=wm+(j8&1)*8+r8, alc=(j8>>1)*8;
    unsigned aH=(unsigned)__cvta_generic_to_shared(&AsH[0][alr][alc]);
    unsigned aL=(unsigned)__cvta_generic_to_shared(&AsL[0][alr][alc]);

    // ---- phase loop: phase p does layer0(t=p) and layer1(t=p-1); ONE barrier ----
    #pragma unroll 1
    for (int p=0;p<=L_SEQ;++p){
        if (p<L_SEQ){
            const int pe=p&1;   // h0[p] parity
            const __nv_bfloat16* h0pH=g_h[pe?0:2]; const __nv_bfloat16* h0pL=g_h[pe?1:3];
            __nv_bfloat16* h0cH=g_h[pe?2:0];       __nv_bfloat16* h0cL=g_h[pe?3:1];

            const float* xa=seq+((size_t)p*NB+mb)*6;
            for (int i=tid;i<128*6;i+=NTHR){ int r=i/6,k=i-r*6; Xs[r][k]=xa[r*6+k]; }

            float acc[4][2][4];
            #pragma unroll
            for (int a=0;a<4;++a)
                #pragma unroll
                for (int b=0;b<2;++b){ acc[a][b][0]=0.f;acc[a][b][1]=0.f;acc[a][b][2]=0.f;acc[a][b][3]=0.f; }

            gemm_pipe(h0pH+mb*HID+Aoff,h0pL+mb*HID+Aoff,g_Wp[0],g_Wp[1],jn0,lane,pH,pL,aH,aL,acc);

            #pragma unroll
            for (int mt=0;mt<4;++mt)
                #pragma unroll
                for (int nt=0;nt<2;++nt)
                    #pragma unroll
                    for (int c=0;c<4;++c){
                        int r=wm+mt*16+gq+((c>>1)<<3);
                        int nl=wn+nt*8+2*iq+(c&1);
                        float sx=0.f;
                        #pragma unroll
                        for (int k=0;k<6;++k) sx+=Xs[r][k]*W6s[nl][k];
                        acc[mt][nt][c]+=sx;
                    }
            // epilogue layer0
            #pragma unroll
            for (int mt=0;mt<4;++mt)
                #pragma unroll
                for (int nt=0;nt<2;++nt){
                    float c0=acc[mt][nt][0],c1=acc[mt][nt][1],c2=acc[mt][nt][2],c3=acc[mt][nt][3];
                    float v0=__shfl_xor_sync(~0u,c0,1), v1=__shfl_xor_sync(~0u,c1,1);
                    float v2=__shfl_xor_sync(~0u,c2,1), v3=__shfl_xor_sync(~0u,c3,1);
                    float zi,zf,zg,zo; int row;
                    if(!odd){ zi=c0;zf=c1;zg=v0;zo=v1;row=gq; } else { zi=v2;zf=v3;zg=c2;zo=c3;row=gq+8; }
                    int ul=(wn>>2)+nt*2+(iq>>1);
                    float4 bb=*(const float4*)&biasS0[ul<<2];
                    float ii=sigm(zi+bb.x), ff=sigm(zf+bb.y), gg=ftanh(zg+bb.z), oo=sigm(zo+bb.w);
                    int m=mb+wm+mt*16+row;
                    int idx=m*HID+(s<<4)+ul;
                    float c=ff*g_c0[idx]+ii*gg;
                    g_c0[idx]=c;
                    float hv=oo*ftanh(c);
                    __nv_bfloat16 hh=__float2bfloat16(hv);
                    h0cH[idx]=hh; h0cL[idx]=__float2bfloat16(hv-__bfloat162float(hh));
                }
        }
        if (p>=1){
            const int t=p-1, te=t&1;
            const __nv_bfloat16* h0tH=g_h[te?2:0]; const __nv_bfloat16* h0tL=g_h[te?3:1];
            const __nv_bfloat16* h1pH=g_h[te?4:6]; const __nv_bfloat16* h1pL=g_h[te?5:7];
            __nv_bfloat16* h1cH=g_h[te?6:4];       __nv_bfloat16* h1cL=g_h[te?7:5];

            float acc[4][2][4];
            #pragma unroll
            for (int a=0;a<4;++a)
                #pragma unroll
                for (int b=0;b<2;++b){ acc[a][b][0]=0.f;acc[a][b][1]=0.f;acc[a][b][2]=0.f;acc[a][b][3]=0.f; }

            gemm_pipe(h0tH+mb*HID+Aoff,h0tL+mb*HID+Aoff,g_Wp[2],g_Wp[3],jn0,lane,pH,pL,aH,aL,acc);
            gemm_pipe(h1pH+mb*HID+Aoff,h1pL+mb*HID+Aoff,g_Wp[4],g_Wp[5],jn0,lane,pH,pL,aH,aL,acc);

            #pragma unroll
            for (int mt=0;mt<4;++mt)
                #pragma unroll
                for (int nt=0;nt<2;++nt){
                    float c0=acc[mt][nt][0],c1=acc[mt][nt][1],c2=acc[mt][nt][2],c3=acc[mt][nt][3];
                    float v0=__shfl_xor_sync(~0u,c0,1), v1=__shfl_xor_sync(~0u,c1,1);
                    float v2=__shfl_xor_sync(~0u,c2,1), v3=__shfl_xor_sync(~0u,c3,1);
                    float zi,zf,zg,zo; int row;
                    if(!odd){ zi=c0;zf=c1;zg=v0;zo=v1;row=gq; } else { zi=v2;zf=v3;zg=c2;zo=c3;row=gq+8; }
                    int ul=(wn>>2)+nt*2+(iq>>1);
                    float4 bb=*(const float4*)&biasS1[ul<<2];
                    float ii=sigm(zi+bb.x), ff=sigm(zf+bb.y), gg=ftanh(zg+bb.z), oo=sigm(zo+bb.w);
                    int m=mb+wm+mt*16+row;
                    int idx=m*HID+(s<<4)+ul;
                    float c=ff*g_c1[idx]+ii*gg;
                    g_c1[idx]=c;
                    float hv=oo*ftanh(c);
                    __nv_bfloat16 hh=__float2bfloat16(hv);
                    h1cH[idx]=hh; h1cL[idx]=__float2bfloat16(hv-__bfloat162float(hh));
                }
        }
        grid_sync();
    }

    // ---- final linear on h1[511] (odd -> g_h[6],g_h[7]) ----
    #pragma unroll 1
    for (int r=0;r<2;++r){
        int row=bid*2+r;
        float ssum=0.f;
        for (int k=tid;k<HID;k+=NTHR){
            int idx=row*HID+k;
            ssum+=(__bfloat162float(g_h[6][idx])+__bfloat162float(g_h[7][idx]))*linW[k];
        }
        #pragma unroll
        for (int o=16;o;o>>=1) ssum+=__shfl_down_sync(~0u,ssum,o);
        if ((tid&31)==0) red[tid>>5]=ssum;
        __syncthreads();
        if (tid==0) out[row]=red[0]+red[1]+red[2]+red[3]+red[4]+red[5]+red[6]+red[7]+linb[0];
        __syncthreads();
    }
}

extern "C" void kernel_launch(void* const* d_in, const int* in_sizes, int n_in,
                              void* d_out, int out_size)
{
    (void)in_sizes;(void)n_in;(void)out_size;
    lstm_tc3<<<NBLK,NTHR>>>(
        (const float*)d_in[0],
        (const float*)d_in[1],(const float*)d_in[2],
        (const float*)d_in[3],(const float*)d_in[4],
        (const float*)d_in[5],(const float*)d_in[6],
        (const float*)d_in[7],(const float*)d_in[8],
        (const float*)d_in[9],(const float*)d_in[10],
        (float*)d_out);
}

// round 13
// speedup vs baseline: 1.1655x; 1.1655x over previous
#include <cuda_runtime.h>
#include <cuda_bf16.h>
#include <math.h>

#define HID   1024
#define NB    256
#define L_SEQ 512
#define NH    (NB * HID)
#define NBLK  128
#define NTHR  256
#define NFRAG (512 * 64 * 32)   // 512 n-groups * 64 k-tiles * 32 lanes

// packed B fragments: [0]=Whh0 hi [1]=Whh0 lo [2]=Wih1 hi [3]=Wih1 lo [4]=Whh1 hi [5]=Whh1 lo
__device__ uint2         g_Wp[6][NFRAG];
__device__ __nv_bfloat16 g_h[8][NH];     // h0a hi/lo, h0b hi/lo, h1a hi/lo, h1b hi/lo
__device__ float         g_c0[NH], g_c1[NH];
__device__ unsigned      g_count = 0, g_gen = 0;

__device__ __forceinline__ float sigm(float x){ return __fdividef(1.f, 1.f + __expf(-x)); }
__device__ __forceinline__ float ftanh(float x){ float e=__expf(2.f*x); return 1.f-__fdividef(2.f,e+1.f); }
// packed col p (0..4095) -> weight row: unit-major within 64-col slice
__device__ __forceinline__ int colmap(int p){ int s=p>>6, nl=p&63; return (nl&3)*HID + (s<<4) + (nl>>2); }
__device__ __forceinline__ unsigned pkbf(__nv_bfloat16 a,__nv_bfloat16 b){
    __nv_bfloat162 t; t.x=a; t.y=b; return *reinterpret_cast<unsigned*>(&t); }

__device__ __forceinline__ void grid_sync(){
    __syncthreads();
    if (threadIdx.x==0){
        __threadfence();
        unsigned g=*(volatile unsigned*)&g_gen;
        if (atomicAdd(&g_count,1u)==NBLK-1){ g_count=0; __threadfence(); atomicAdd(&g_gen,1u); }
        else while (*(volatile unsigned*)&g_gen==g){}
        __threadfence();
    }
    __syncthreads();
}

#define MMA(d,a,b0v,b1v) asm volatile( \
  "mma.sync.aligned.m16n8k16.row.col.f32.bf16.bf16.f32 {%0,%1,%2,%3},{%4,%5,%6,%7},{%8,%9},{%0,%1,%2,%3};" \
  : "+f"(d[0]),"+f"(d[1]),"+f"(d[2]),"+f"(d[3]) \
  : "r"(a[0]),"r"(a[1]),"r"(a[2]),"r"(a[3]),"r"(b0v),"r"(b1v))
#define LDSM4(r,addr) asm volatile( \
  "ldmatrix.sync.aligned.m8n8.x4.shared.b16 {%0,%1,%2,%3},[%4];" \
  : "=r"(r[0]),"=r"(r[1]),"=r"(r[2]),"=r"(r[3]) : "r"(addr))

// GEMM-accumulate over K=1024, block tile 128m x 64n, warp tile 64m x 16n.
// MMA issue order: 3 passes of 8 INDEPENDENT MMAs each (dependent-op distance 8
// instead of 1) — per-accumulator accumulation order unchanged (bit-identical).
__device__ __forceinline__ void gemm_k1024(
    const __nv_bfloat16* __restrict__ Ahi, const __nv_bfloat16* __restrict__ Alo,
    const uint2* __restrict__ Bhi, const uint2* __restrict__ Blo,
    int jn0, int lane, int tid, unsigned aHb, unsigned aLb,
    __nv_bfloat16 (*AsH)[40], __nv_bfloat16 (*AsL)[40], float (&acc)[4][2][4])
{
    const int srow = tid>>1, scol = (tid&1)*16;
    const __nv_bfloat16* gh = Ahi + srow*HID + scol;
    const __nv_bfloat16* gl = Alo + srow*HID + scol;
    uint4 ph0=__ldcg((const uint4*)gh),     ph1=__ldcg((const uint4*)(gh+8));
    uint4 pl0=__ldcg((const uint4*)gl),     pl1=__ldcg((const uint4*)(gl+8));

    #pragma unroll 1
    for (int k0=0; k0<HID; k0+=32){
        const int kt=k0>>4;
        uint2 bh[2][2], bl[2][2];
        #pragma unroll
        for (int h=0;h<2;++h)
            #pragma unroll
            for (int nt=0;nt<2;++nt){
                int idx=((jn0+nt)*64 + kt+h)*32 + lane;
                bh[h][nt]=Bhi[idx]; bl[h][nt]=Blo[idx];
            }
        __syncthreads();
        *(uint4*)&AsH[srow][scol]=ph0; *(uint4*)&AsH[srow][scol+8]=ph1;
        *(uint4*)&AsL[srow][scol]=pl0; *(uint4*)&AsL[srow][scol+8]=pl1;
        __syncthreads();
        if (k0+32<HID){
            ph0=__ldcg((const uint4*)(gh+k0+32)); ph1=__ldcg((const uint4*)(gh+k0+40));
            pl0=__ldcg((const uint4*)(gl+k0+32)); pl1=__ldcg((const uint4*)(gl+k0+40));
        }
        #pragma unroll
        for (int h=0;h<2;++h){
            unsigned ah[4][4], al[4][4];
            #pragma unroll
            for (int mt=0;mt<4;++mt){ LDSM4(ah[mt], aHb+mt*1280+h*32); LDSM4(al[mt], aLb+mt*1280+h*32); }
            // pass 1: ah*bh — 8 independent MMAs
            #pragma unroll
            for (int mt=0;mt<4;++mt)
                #pragma unroll
                for (int nt=0;nt<2;++nt)
                    MMA(acc[mt][nt], ah[mt], bh[h][nt].x, bh[h][nt].y);
            // pass 2: ah*bl — 8 independent MMAs
            #pragma unroll
            for (int mt=0;mt<4;++mt)
                #pragma unroll
                for (int nt=0;nt<2;++nt)
                    MMA(acc[mt][nt], ah[mt], bl[h][nt].x, bl[h][nt].y);
            // pass 3: al*bh — 8 independent MMAs
            #pragma unroll
            for (int mt=0;mt<4;++mt)
                #pragma unroll
                for (int nt=0;nt<2;++nt)
                    MMA(acc[mt][nt], al[mt], bh[h][nt].x, bh[h][nt].y);
        }
    }
}

__global__ void __launch_bounds__(NTHR,1) lstm_tc(
    const float* __restrict__ seq,
    const float* __restrict__ Wih0, const float* __restrict__ Whh0,
    const float* __restrict__ bih0, const float* __restrict__ bhh0,
    const float* __restrict__ Wih1, const float* __restrict__ Whh1,
    const float* __restrict__ bih1, const float* __restrict__ bhh1,
    const float* __restrict__ linW, const float* __restrict__ linb,
    float* __restrict__ out)
{
    __shared__ __nv_bfloat16 AsH[128][40], AsL[128][40];
    __shared__ float Xs[128][6], W6s[64][6];
    __shared__ __align__(16) float biasS0[64], biasS1[64];
    __shared__ float red[8];

    const int tid=threadIdx.x, bid=blockIdx.x, lane=tid&31, w=tid>>5;
    const int s=bid>>1, mb=(bid&1)*128;        // n-slice (16 units), batch half
    const int wm=(w&1)*64, wn=(w>>1)*16;       // warp tile bases
    const int jn0=s*8+(wn>>3);
    const int gq=lane>>2, iq=lane&3, odd=iq&1;

    // ---- pack weights into B-fragment layout (once per launch) ----
    {
        const float* Wsrc[3]={Whh0,Wih1,Whh1};
        for (int f=bid*8+w; f<3*32768; f+=NBLK*8){
            int mat=f>>15, rem=f&32767, jn=rem>>6, kt=rem&63;
            int j=colmap(jn*8+(lane>>2));
            int k0=(kt<<4)+(lane&3)*2;
            const float* W=Wsrc[mat]+j*HID+k0;
            float2 w0=*(const float2*)W, w8=*(const float2*)(W+8);
            __nv_bfloat16 h0=__float2bfloat16(w0.x), h1=__float2bfloat16(w0.y);
            __nv_bfloat16 h2=__float2bfloat16(w8.x), h3=__float2bfloat16(w8.y);
            __nv_bfloat16 l0=__float2bfloat16(w0.x-__bfloat162float(h0));
            __nv_bfloat16 l1=__float2bfloat16(w0.y-__bfloat162float(h1));
            __nv_bfloat16 l2=__float2bfloat16(w8.x-__bfloat162float(h2));
            __nv_bfloat16 l3=__float2bfloat16(w8.y-__bfloat162float(h3));
            int idx=(jn*64+kt)*32+lane;
            g_Wp[mat*2  ][idx]=make_uint2(pkbf(h0,h1),pkbf(h2,h3));
            g_Wp[mat*2+1][idx]=make_uint2(pkbf(l0,l1),pkbf(l2,l3));
        }
    }
    // ---- zero initial states ----
    {
        int base=bid*(NH/NBLK); __nv_bfloat16 z=__float2bfloat16(0.f);
        for (int i=tid;i<NH/NBLK;i+=NTHR){
            g_h[0][base+i]=z; g_h[1][base+i]=z; g_h[4][base+i]=z; g_h[5][base+i]=z;
            g_c0[base+i]=0.f; g_c1[base+i]=0.f;
        }
    }
    if (tid<64){
        int j=colmap(s*64+tid);
        biasS0[tid]=bih0[j]+bhh0[j]; biasS1[tid]=bih1[j]+bhh1[j];
    }
    for (int i=tid;i<64*6;i+=NTHR){ int c=i/6,k=i-c*6; W6s[c][k]=Wih0[colmap(s*64+c)*6+k]; }
    grid_sync();

    // ldmatrix per-lane addresses
    const int j8=lane>>3, r8=lane&7;
    const int alr=wm+(j8&1)*8+r8, alc=(j8>>1)*8;
    unsigned aHb=(unsigned)__cvta_generic_to_shared(&AsH[alr][alc]);
    unsigned aLb=(unsigned)__cvta_generic_to_shared(&AsL[alr][alc]);

    #pragma unroll 1
    for (int t=0;t<L_SEQ;++t){
        const __nv_bfloat16 *h0pH,*h0pL,*h1pH,*h1pL; __nv_bfloat16 *h0cH,*h0cL,*h1cH,*h1cL;
        if (t&1){ h0pH=g_h[2];h0pL=g_h[3];h0cH=g_h[0];h0cL=g_h[1];
                  h1pH=g_h[6];h1pL=g_h[7];h1cH=g_h[4];h1cL=g_h[5]; }
        else    { h0pH=g_h[0];h0pL=g_h[1];h0cH=g_h[2];h0cL=g_h[3];
                  h1pH=g_h[4];h1pL=g_h[5];h1cH=g_h[6];h1cL=g_h[7]; }

        for (int layer=0;layer<2;++layer){
            float acc[4][2][4];
            #pragma unroll
            for (int a=0;a<4;++a){ acc[a][0][0]=acc[a][0][1]=acc[a][0][2]=acc[a][0][3]=0.f;
                                   acc[a][1][0]=acc[a][1][1]=acc[a][1][2]=acc[a][1][3]=0.f; }
            if (layer==0){
                const float* xa=seq+((size_t)t*NB+mb)*6;
                for (int i=tid;i<128*6;i+=NTHR){ int r=i/6,k=i-r*6; Xs[r][k]=xa[r*6+k]; }
                // Xs made visible by first __syncthreads inside gemm
                gemm_k1024(h0pH+mb*HID,h0pL+mb*HID,g_Wp[0],g_Wp[1],jn0,lane,tid,aHb,aLb,AsH,AsL,acc);
                // x projection K=6 in fragment layout
                #pragma unroll
                for (int mt=0;mt<4;++mt)
                    #pragma unroll
                    for (int nt=0;nt<2;++nt)
                        #pragma unroll
                        for (int c=0;c<4;++c){
                            int r=wm+mt*16+gq+((c>>1)<<3);
                            int nl=wn+nt*8+2*iq+(c&1);
                            float sx=0.f;
                            #pragma unroll
                            for (int k=0;k<6;++k) sx+=Xs[r][k]*W6s[nl][k];
                            acc[mt][nt][c]+=sx;
                        }
            } else {
                gemm_k1024(h0cH+mb*HID,h0cL+mb*HID,g_Wp[2],g_Wp[3],jn0,lane,tid,aHb,aLb,AsH,AsL,acc);
                gemm_k1024(h1pH+mb*HID,h1pL+mb*HID,g_Wp[4],g_Wp[5],jn0,lane,tid,aHb,aLb,AsH,AsL,acc);
            }
            // epilogue: shfl_xor(1) pairs share a unit; even lane -> row gq, odd -> row gq+8
            const float* bS=(layer==0)?biasS0:biasS1;
            float* Cst=(layer==0)?g_c0:g_c1;
            __nv_bfloat16* Hh=(layer==0)?h0cH:h1cH;
            __nv_bfloat16* Hl=(layer==0)?h0cL:h1cL;
            #pragma unroll
            for (int mt=0;mt<4;++mt)
                #pragma unroll
                for (int nt=0;nt<2;++nt){
                    float c0=acc[mt][nt][0],c1=acc[mt][nt][1],c2=acc[mt][nt][2],c3=acc[mt][nt][3];
                    float v0=__shfl_xor_sync(~0u,c0,1), v1=__shfl_xor_sync(~0u,c1,1);
                    float v2=__shfl_xor_sync(~0u,c2,1), v3=__shfl_xor_sync(~0u,c3,1);
                    float zi,zf,zg,zo; int row;
                    if(!odd){ zi=c0;zf=c1;zg=v0;zo=v1;row=gq; } else { zi=v2;zf=v3;zg=c2;zo=c3;row=gq+8; }
                    int ul=(wn>>2)+nt*2+(iq>>1);
                    float4 bb=*(const float4*)&bS[ul<<2];
                    float ii=sigm(zi+bb.x), ff=sigm(zf+bb.y), gg=ftanh(zg+bb.z), oo=sigm(zo+bb.w);
                    int m=mb+wm+mt*16+row;
                    int idx=m*HID+(s<<4)+ul;
                    float c=ff*Cst[idx]+ii*gg;
                    Cst[idx]=c;
                    float hv=oo*ftanh(c);
                    __nv_bfloat16 hh=__float2bfloat16(hv);
                    Hh[idx]=hh; Hl[idx]=__float2bfloat16(hv-__bfloat162float(hh));
                }
            grid_sync();
        }
    }

    // ---- final linear on last h1 (t=511 odd -> wrote g_h[4]/g_h[5]) ----
    #pragma unroll 1
    for (int r=0;r<2;++r){
        int row=bid*2+r;
        float ssum=0.f;
        for (int k=tid;k<HID;k+=NTHR){
            int idx=row*HID+k;
            float hv=__bfloat162float(g_h[4][idx])+__bfloat162float(g_h[5][idx]);
            ssum+=hv*linW[k];
        }
        #pragma unroll
        for (int o=16;o;o>>=1) ssum+=__shfl_down_sync(~0u,ssum,o);
        if ((tid&31)==0) red[tid>>5]=ssum;
        __syncthreads();
        if (tid==0) out[row]=red[0]+red[1]+red[2]+red[3]+red[4]+red[5]+red[6]+red[7]+linb[0];
        __syncthreads();
    }
}

extern "C" void kernel_launch(void* const* d_in, const int* in_sizes, int n_in,
                              void* d_out, int out_size)
{
    (void)in_sizes;(void)n_in;(void)out_size;
    lstm_tc<<<NBLK,NTHR>>>(
        (const float*)d_in[0],
        (const float*)d_in[1],(const float*)d_in[2],
        (const float*)d_in[3],(const float*)d_in[4],
        (const float*)d_in[5],(const float*)d_in[6],
        (const float*)d_in[7],(const float*)d_in[8],
        (const float*)d_in[9],(const float*)d_in[10],
        (float*)d_out);
}